// round 1
// baseline (speedup 1.0000x reference)
#include <cuda_runtime.h>
#include <cuda_bf16.h>

// Problem constants
#define H 128
#define W 128
#define HW (H * W)          // 16384
#define C 32
#define KK 81               // 9x9
#define KS 9
#define DIL 2
#define PAD 8

// Scratch (device globals; no allocations allowed)
__device__ __align__(16) float g_k[KK * HW];       // guidance kernel  [ij][p]
__device__ __align__(16) float g_h[C * HW];        // layer-1 output   [c][p]
__device__ __align__(16) float g_w1t[KK * C * C];  // W1 transposed    [ij][c][o]
__device__ __align__(16) float g_w2t[KK * C * C];  // W2 transposed    [ij][c][o]

// ---------------------------------------------------------------------------
// Transpose weights (O,C,9,9) -> (81, C, O) so per-offset slices are
// contiguous 4KB blocks (coalesced smem staging in the conv kernels).
// ---------------------------------------------------------------------------
__global__ void prep_w(const float* __restrict__ W1, const float* __restrict__ W2) {
    int t = blockIdx.x * blockDim.x + threadIdx.x;
    const int N = KK * C * C;  // 82944
    if (t >= 2 * N) return;
    const float* Wsrc = (t < N) ? W1 : W2;
    float* Wdst = (t < N) ? g_w1t : g_w2t;
    int e = (t < N) ? t : (t - N);
    int ij = e >> 10;           // /1024
    int c = (e >> 5) & 31;
    int o = e & 31;
    Wdst[e] = Wsrc[o * (C * KK) + c * KK + ij];
}

// ---------------------------------------------------------------------------
// Guidance kernel: k[ij][p] = exp(-0.5 * sum_c (f[c, p+off] - f[c,p])^2)
// OOB neighbors are zero-padded -> sum = ||f_center||^2.
// grid.y splits the 81 offsets into 3 groups of 27 for occupancy.
// ---------------------------------------------------------------------------
__global__ void compute_k(const float* __restrict__ f) {
    int p = blockIdx.x * blockDim.x + threadIdx.x;  // 16384 pixels
    int h = p >> 7;
    int w = p & 127;

    float fc[C];
#pragma unroll
    for (int c = 0; c < C; c++) fc[c] = __ldg(f + c * HW + p);
    float normc = 0.f;
#pragma unroll
    for (int c = 0; c < C; c++) normc = fmaf(fc[c], fc[c], normc);

    int ij0 = blockIdx.y * 27;
#pragma unroll 1
    for (int s = 0; s < 27; s++) {
        int ij = ij0 + s;
        int hh = h + (ij / KS) * DIL - PAD;
        int ww = w + (ij % KS) * DIL - PAD;
        float acc;
        if ((unsigned)hh < (unsigned)H && (unsigned)ww < (unsigned)W) {
            const float* fp = f + hh * W + ww;
            acc = 0.f;
#pragma unroll
            for (int c = 0; c < C; c++) {
                float d = __ldg(fp + c * HW) - fc[c];
                acc = fmaf(d, d, acc);
            }
        } else {
            acc = normc;
        }
        g_k[ij * HW + p] = __expf(-0.5f * acc);
    }
}

// ---------------------------------------------------------------------------
// Pixel-adaptive conv:
//   out[o][p] = b[o] + sum_{ij,c} Wt[ij][c][o] * k[ij][p] * xin[c][p+off(ij)]
// Block: 256 threads = 64 consecutive pixels x 4 output-channel groups.
// Each thread: 1 pixel, 8 output channels in registers.
// Weights staged in dynamic smem, 27 offset-slices (108KB) per chunk.
// ---------------------------------------------------------------------------
#define CHUNK 27

__global__ void pacconv_kernel(const float* __restrict__ xin,
                               const float* __restrict__ Wt,
                               const float* __restrict__ bias,
                               float* __restrict__ out) {
    extern __shared__ float Wsm[];  // CHUNK * 1024 floats
    int tid = threadIdx.x;
    int og = tid >> 6;                       // 0..3 output group
    int p = blockIdx.x * 64 + (tid & 63);    // pixel
    int h = p >> 7;
    int w = p & 127;

    float acc[8];
#pragma unroll
    for (int o = 0; o < 8; o++) acc[o] = __ldg(bias + og * 8 + o);

#pragma unroll 1
    for (int chunk = 0; chunk < 3; chunk++) {
        __syncthreads();
        // cooperative stage of 27 weight slices (27648 floats = 6912 float4)
        {
            const float4* src = (const float4*)(Wt + chunk * CHUNK * 1024);
            float4* dst = (float4*)Wsm;
#pragma unroll
            for (int r = 0; r < CHUNK; r++) dst[r * 256 + tid] = src[r * 256 + tid];
        }
        __syncthreads();

#pragma unroll 1
        for (int s = 0; s < CHUNK; s++) {
            int ij = chunk * CHUNK + s;
            int hh = h + (ij / KS) * DIL - PAD;
            int ww = w + (ij % KS) * DIL - PAD;
            if ((unsigned)hh >= (unsigned)H || (unsigned)ww >= (unsigned)W) continue;

            float kv = __ldg(g_k + ij * HW + p);
            const float* xp = xin + hh * W + ww;
            const float* wrow = Wsm + s * 1024 + og * 8;

#pragma unroll 4
            for (int c = 0; c < C; c++) {
                float xv = __ldg(xp + c * HW) * kv;
                float4 w0 = *(const float4*)(wrow + c * 32);
                float4 w1 = *(const float4*)(wrow + c * 32 + 4);
                acc[0] = fmaf(xv, w0.x, acc[0]);
                acc[1] = fmaf(xv, w0.y, acc[1]);
                acc[2] = fmaf(xv, w0.z, acc[2]);
                acc[3] = fmaf(xv, w0.w, acc[3]);
                acc[4] = fmaf(xv, w1.x, acc[4]);
                acc[5] = fmaf(xv, w1.y, acc[5]);
                acc[6] = fmaf(xv, w1.z, acc[6]);
                acc[7] = fmaf(xv, w1.w, acc[7]);
            }
        }
    }

#pragma unroll
    for (int o = 0; o < 8; o++) out[(og * 8 + o) * HW + p] = acc[o];
}

// ---------------------------------------------------------------------------
extern "C" void kernel_launch(void* const* d_in, const int* in_sizes, int n_in,
                              void* d_out, int out_size) {
    const float* x = (const float*)d_in[0];
    const float* f = (const float*)d_in[1];
    const float* W1 = (const float*)d_in[2];
    const float* b1 = (const float*)d_in[3];
    const float* W2 = (const float*)d_in[4];
    const float* b2 = (const float*)d_in[5];
    float* out = (float*)d_out;

    float* kbuf;  cudaGetSymbolAddress((void**)&kbuf, g_k);
    float* hbuf;  cudaGetSymbolAddress((void**)&hbuf, g_h);
    float* w1t;   cudaGetSymbolAddress((void**)&w1t, g_w1t);
    float* w2t;   cudaGetSymbolAddress((void**)&w2t, g_w2t);
    (void)kbuf;

    const int smem = CHUNK * 1024 * sizeof(float);  // 110592 bytes
    cudaFuncSetAttribute(pacconv_kernel, cudaFuncAttributeMaxDynamicSharedMemorySize, smem);

    // 1. transpose weights
    prep_w<<<(2 * KK * C * C + 255) / 256, 256>>>(W1, W2);

    // 2. guidance kernel
    dim3 gk(HW / 256, 3);
    compute_k<<<gk, 256>>>(f);

    // 3. layer 1: x -> g_h
    pacconv_kernel<<<HW / 64, 256, smem>>>(x, w1t, b1, hbuf);

    // 4. layer 2: g_h -> out
    pacconv_kernel<<<HW / 64, 256, smem>>>(hbuf, w2t, b2, out);
}